// round 15
// baseline (speedup 1.0000x reference)
#include <cuda_runtime.h>
#include <cuda_bf16.h>
#include <math.h>

#define B_   16
#define T_   500
#define D_   512
#define N_   128
#define E_   640
#define H_   1024
#define A_   1024
#define P_   1024
#define V_   10025
#define KIH  1152              // E_ + D_
#define KRO  2176              // H_ + E_ + D_
#define ZH_  0.05f
#define NBLK 148               // persistent grid: 1 block/SM
#define NG_  4                 // batch groups
#define SG_  37                // blocks per group
#define NT_  512               // threads per loop block
#define KSA  6                 // A-phase k-splits
#define KSB  16                // B-phase k-splits

// ----------------------------- scratch ------------------------------------
__device__ __align__(16) float g_encctx[B_ * T_ * A_];
__device__ __align__(16) float g_invf[B_ * T_];
__device__ __align__(16) float g_h2[2 * H_ * B_];  // double-buffered h [k][b]
__device__ __align__(16) float g_ctx_t[D_ * B_];   // ctx transposed [d][b]
__device__ __align__(16) float g_accum[B_ * T_];
__device__ __align__(16) float g_energy[B_ * T_];
__device__ __align__(16) float g_gemb[B_ * N_ * 3 * H_];
__device__ __align__(16) float g_rin[B_ * N_ * KRO];
__device__ __align__(16) float g_ro[B_ * N_ * (P_ / 2)];
__device__ __align__(16) float g_wih_e[3 * H_ * E_];
__device__ __align__(16) float g_wct[D_ * 3 * H_]; // ctx-part, k-major
__device__ __align__(16) float g_ws_t[H_ * A_];    // W_s^T [k][a]
__device__ __align__(16) float g_b3[3 * H_];
__device__ __align__(16) float g_pgA[NG_ * KSA * 3 * H_ * 4];
__device__ __align__(16) float g_pgB[NG_ * KSB * A_ * 4];
__device__ int   g_lab64;
// monotonic flag barriers (no reset needed across graph replays)
__device__ unsigned g_flag[NG_][64];
__device__ unsigned g_flagG[192];

// ----------------------------- helpers ------------------------------------
__device__ __forceinline__ float fsig(float x) {
    return __fdividef(1.0f, 1.0f + __expf(-x));
}
__device__ __forceinline__ float ftanh(float x) {
    float a = fabsf(x);
    float e = __expf(-2.0f * a);
    float r = __fdividef(1.0f - e, 1.0f + e);
    return copysignf(r, x);
}
__device__ __forceinline__ unsigned pack_h2(float lo, float hi) {
    unsigned r;
    asm("cvt.rn.f16x2.f32 %0, %1, %2;" : "=r"(r) : "f"(hi), "f"(lo));
    return r;
}
__device__ __forceinline__ unsigned h2tanh(unsigned x) {
    unsigned y;
    asm("tanh.approx.f16x2 %0, %1;" : "=r"(y) : "r"(x));
    return y;
}
#define HFMA2U(acc, a, b) \
    asm("fma.rn.f16x2 %0, %1, %2, %0;" : "+r"(acc) : "r"(a), "r"(b))
__device__ __forceinline__ unsigned hadd2u(unsigned a, unsigned b) {
    unsigned r;
    asm("add.rn.f16x2 %0, %1, %2;" : "=r"(r) : "r"(a), "r"(b));
    return r;
}
__device__ __forceinline__ float2 h2f2(unsigned u) {
    __half2 h;
    memcpy(&h, &u, 4);
    return __half22float2(h);
}
__device__ __forceinline__ unsigned long long packf2(float lo, float hi) {
    unsigned long long r;
    asm("mov.b64 %0, {%1, %2};" : "=l"(r) : "f"(lo), "f"(hi));
    return r;
}
#define FMA2(acc, a, b) \
    asm("fma.rn.f32x2 %0, %1, %2, %0;" : "+l"(acc) : "l"(a), "l"(b))
__device__ __forceinline__ void unpackf2(unsigned long long v, float& lo, float& hi) {
    asm("mov.b64 {%0, %1}, %2;" : "=f"(lo), "=f"(hi) : "l"(v));
}

__device__ __forceinline__ void stgrel(unsigned* p, unsigned v) {
    asm volatile("st.release.gpu.u32 [%0], %1;" :: "l"(p), "r"(v) : "memory");
}
__device__ __forceinline__ unsigned ldgacq(unsigned* p) {
    unsigned v;
    asm volatile("ld.acquire.gpu.u32 %0, [%1];" : "=r"(v) : "l"(p) : "memory");
    return v;
}
// parallel-arrival flag barrier: block idx writes its own slot; cnt threads
// poll all slots. Tags are monotonic; signed compare handles wraparound.
__device__ __forceinline__ void flagbar(unsigned* flags, int idx, int cnt,
                                        unsigned tag) {
    __syncthreads();
    if (threadIdx.x == 0) stgrel(&flags[idx], tag);
    if (threadIdx.x < (unsigned)cnt) {
        while ((int)(ldgacq(&flags[threadIdx.x]) - tag) < 0) { }
    }
    __syncthreads();
}

// ------------------------ labels dtype detection ---------------------------
__global__ void k_detect(const int* __restrict__ lab32) {
    int ok = 1;
    for (int i = threadIdx.x; i < 1024; i += blockDim.x)
        if (lab32[2 * i + 1] != 0) ok = 0;
    int all = __syncthreads_and(ok);
    if (threadIdx.x == 0) g_lab64 = all;
}

// ========== merged prologue: gather | pack | twct | tws | invf =============
__global__ void __launch_bounds__(256) k_prep(const void* __restrict__ labels,
                                              const float* __restrict__ embed,
                                              const float* __restrict__ W_ih,
                                              const float* __restrict__ b_ih,
                                              const float* __restrict__ b_hh,
                                              const float* __restrict__ W_s,
                                              const float* __restrict__ enc,
                                              const float* __restrict__ wf) {
    __shared__ float tl[32][33];
    int bid = blockIdx.x;
    int tid = threadIdx.x;

    if (bid < 2048) {                      // ---- shifted embedding gather
        int row = bid;
        int n = row & (N_ - 1);
        int b = row >> 7;
        float4* dst = (float4*)(g_rin + (size_t)row * KRO + H_);
        if (n == 0) {
            for (int k = tid; k < E_ / 4; k += 256)
                dst[k] = make_float4(0.f, 0.f, 0.f, 0.f);
            return;
        }
        int idx = b * N_ + n - 1;
        int lab = g_lab64 ? (int)((const long long*)labels)[idx]
                          : ((const int*)labels)[idx];
        if (lab < 0) lab = 0;
        if (lab >= V_) lab = V_ - 1;
        const float4* src = (const float4*)(embed + (size_t)lab * E_);
        for (int k = tid; k < E_ / 4; k += 256) dst[k] = src[k];
    } else if (bid < 5120) {               // ---- pack emb-part rows + biases
        int jj = bid - 2048;
        int src = (jj < 1024) ? jj : jj + 1024;
        const float* s = W_ih + (size_t)src * KIH;
        for (int k = tid; k < E_; k += 256)
            g_wih_e[(size_t)jj * E_ + k] = s[k];
        if (tid == 0) g_b3[jj] = b_ih[src] + b_hh[src];
    } else if (bid < 6656) {               // ---- transpose ctx-part of W_ih
        int i = bid - 5120;
        int gc0 = (i % 96) * 32, k0 = (i / 96) * 32;
        int tx = tid & 31, ty = tid >> 5;
        for (int r = ty; r < 32; r += 8) {
            int gc = gc0 + r;
            int src = (gc < 1024) ? gc : gc + 1024;
            tl[r][tx] = W_ih[(size_t)src * KIH + E_ + k0 + tx];
        }
        __syncthreads();
        for (int r = ty; r < 32; r += 8)
            g_wct[(size_t)(k0 + r) * (3 * H_) + gc0 + tx] = tl[tx][r];
    } else if (bid < 7680) {               // ---- transpose W_s
        int i = bid - 6656;
        int j0 = (i % 32) * 32, k0 = (i / 32) * 32;
        int tx = tid & 31, ty = tid >> 5;
        for (int r = ty; r < 32; r += 8)
            tl[r][tx] = W_s[(size_t)(j0 + r) * H_ + k0 + tx];
        __syncthreads();
        for (int r = ty; r < 32; r += 8)
            g_ws_t[(size_t)(k0 + r) * A_ + j0 + tx] = tl[tx][r];
    } else {                               // ---- inverse fertility
        float* wsh = &tl[0][0];
        for (int i = tid; i < D_; i += 256) wsh[i] = wf[i];
        __syncthreads();
        int row  = (bid - 7680) * 8 + (tid >> 5);
        int lane = tid & 31;
        if (row >= B_ * T_) return;
        const float4* ep = (const float4*)(enc + (size_t)row * D_);
        const float4* wp = (const float4*)wsh;
        float acc = 0.0f;
#pragma unroll
        for (int i = 0; i < 4; i++) {
            float4 e = ep[i * 32 + lane];
            float4 w = wp[i * 32 + lane];
            acc = fmaf(e.x, w.x, fmaf(e.y, w.y, fmaf(e.z, w.z, fmaf(e.w, w.w, acc))));
        }
#pragma unroll
        for (int o = 16; o; o >>= 1) acc += __shfl_down_sync(0xffffffffu, acc, o);
        if (lane == 0) g_invf[row] = 0.5f * fsig(acc);
    }
}

// -------- SGEMM tile: C = A·B^T + bias (f32x2 inner) -----------------------
__device__ __forceinline__ void sgemm_tile(const float* __restrict__ A, int lda,
                                           const float* __restrict__ Bm,
                                           const float* __restrict__ bias,
                                           void* __restrict__ C,
                                           int M, int N, int K, int ldc, int mode,
                                           int bx, int by,
                                           float* As, float* Bs) {
    int tid = threadIdx.x;
    int row0 = by * 128, col0 = bx * 128;
    int tx = tid & 15, ty = tid >> 4;
    unsigned long long acc2[8][4];
#pragma unroll
    for (int i = 0; i < 8; i++)
#pragma unroll
        for (int p = 0; p < 4; p++) acc2[i][p] = 0ULL;
    int lr = tid >> 1;
    int lq = (tid & 1) * 4;
    const float* Ap = A  + (size_t)(row0 + lr) * lda + lq;
    const float* Bp = Bm + (size_t)(col0 + lr) * K + lq;
    bool avalid = (row0 + lr) < M;
    bool bvalid = (col0 + lr) < N;
    for (int k0 = 0; k0 < K; k0 += 8) {
        float4 av = avalid ? *(const float4*)(Ap + k0) : make_float4(0, 0, 0, 0);
        float4 bv = bvalid ? *(const float4*)(Bp + k0) : make_float4(0, 0, 0, 0);
        As[(lq + 0) * 128 + lr] = av.x; As[(lq + 1) * 128 + lr] = av.y;
        As[(lq + 2) * 128 + lr] = av.z; As[(lq + 3) * 128 + lr] = av.w;
        Bs[(lq + 0) * 128 + lr] = bv.x; Bs[(lq + 1) * 128 + lr] = bv.y;
        Bs[(lq + 2) * 128 + lr] = bv.z; Bs[(lq + 3) * 128 + lr] = bv.w;
        __syncthreads();
#pragma unroll
        for (int k = 0; k < 8; k++) {
            float ar[8], br[8];
            *(float4*)(ar)     = *(const float4*)&As[k * 128 + ty * 8];
            *(float4*)(ar + 4) = *(const float4*)&As[k * 128 + ty * 8 + 4];
            *(float4*)(br)     = *(const float4*)&Bs[k * 128 + tx * 8];
            *(float4*)(br + 4) = *(const float4*)&Bs[k * 128 + tx * 8 + 4];
            unsigned long long brp[4];
#pragma unroll
            for (int p = 0; p < 4; p++) brp[p] = packf2(br[2 * p], br[2 * p + 1]);
#pragma unroll
            for (int i = 0; i < 8; i++) {
                unsigned long long aa = packf2(ar[i], ar[i]);
#pragma unroll
                for (int p = 0; p < 4; p++) FMA2(acc2[i][p], aa, brp[p]);
            }
        }
        __syncthreads();
    }
    float acc[8][8];
#pragma unroll
    for (int i = 0; i < 8; i++)
#pragma unroll
        for (int p = 0; p < 4; p++)
            unpackf2(acc2[i][p], acc[i][2 * p], acc[i][2 * p + 1]);
    if (mode == 0) {
        float* Cf = (float*)C;
#pragma unroll
        for (int i = 0; i < 8; i++) {
            int m = row0 + ty * 8 + i;
            if (m >= M) break;
#pragma unroll
            for (int j = 0; j < 8; j++) {
                int nn = col0 + tx * 8 + j;
                if (nn < N) Cf[(size_t)m * ldc + nn] = acc[i][j] + bias[nn];
            }
        }
    } else {
        float* Cf = (float*)C;
#pragma unroll
        for (int i = 0; i < 8; i++) {
            int m = row0 + ty * 8 + i;
            if (m >= M) break;
#pragma unroll
            for (int p = 0; p < 4; p++) {
                int nn = col0 + tx * 8 + p * 2;
                float v0 = acc[i][2 * p]     + bias[nn];
                float v1 = acc[i][2 * p + 1] + bias[nn + 1];
                Cf[(size_t)m * ldc + (nn >> 1)] = fmaxf(v0, v1);
            }
        }
    }
}

// ---- fused pre-GEMMs ------------------------------------------------------
__global__ void __launch_bounds__(256) k_pregemm(const float* __restrict__ enc,
                                                 const float* __restrict__ W_encc,
                                                 const float* __restrict__ b_encc) {
    __shared__ float As[8 * 128], Bs[8 * 128];
    int bid = blockIdx.x;
    if (bid < 504) {
        sgemm_tile(enc, D_, W_encc, b_encc, (void*)g_encctx,
                   B_ * T_, A_, D_, A_, 0, bid % 8, bid / 8, As, Bs);
    } else {
        int i = bid - 504;
        sgemm_tile(g_rin + H_, KRO, g_wih_e, g_b3, (void*)g_gemb,
                   B_ * N_, 3 * H_, E_, 3 * H_, 0, i % 24, i / 24, As, Bs);
    }
}

// --------------------------- post GEMMs ------------------------------------
__global__ void __launch_bounds__(256) k_sgemm(const float* __restrict__ A, int lda,
                                               const float* __restrict__ Bm,
                                               const float* __restrict__ bias,
                                               float* __restrict__ C,
                                               int M, int N, int K, int ldc,
                                               int mode) {
    __shared__ float As[8 * 128], Bs[8 * 128];
    sgemm_tile(A, lda, Bm, bias, (void*)C, M, N, K, ldc, mode,
               blockIdx.x, blockIdx.y, As, Bs);
}

// ====== persistent recurrence: 4 async groups, flag barriers ===============
__global__ void __launch_bounds__(NT_) k_loop(const float* __restrict__ enc,
                                              const int* __restrict__ seqlen,
                                              const float* __restrict__ v_att,
                                              const float* __restrict__ W_fb) {
    __shared__ float sm_f[A_];
    __shared__ __align__(16) unsigned sm_vh[A_ / 2];
    __shared__ float sh_s[A_];
    __shared__ float sm_red[NT_];
    __shared__ float sm_sum[16];
    __shared__ float sw[512];
    __shared__ __align__(16) float sm_stage[86 * 16];   // A ctx staging
    __shared__ __align__(16) float sm_h[64 * 4];        // B h slice
    int tid = threadIdx.x;
    int bk  = blockIdx.x;
    int g   = bk / SG_;
    int lb  = bk % SG_;
    int b0  = g * 4;
    int gw  = bk * NT_ + tid;

    // monotonic barrier tag bases (all slots equal at launch entry)
    unsigned tagg = ldgacq(&g_flag[g][lb]);
    unsigned tagG = ldgacq(&g_flagG[bk]);

    for (int i = tid; i < A_; i += NT_) sm_f[i] = W_fb[i];
    for (int i = tid; i < A_ / 2; i += NT_)
        sm_vh[i] = pack_h2(v_att[2 * i], v_att[2 * i + 1]);
    for (int i = gw; i < 2 * H_ * B_; i += NBLK * NT_) g_h2[i]  = 0.0f;
    for (int i = gw; i < D_ * B_; i += NBLK * NT_) g_ctx_t[i]   = 0.0f;
    for (int i = gw; i < B_ * T_; i += NBLK * NT_) g_accum[i]   = 0.0f;
    flagbar(g_flagG, bk, NBLK, ++tagG);

    int Tb0 = seqlen[b0 + 0], Tb1 = seqlen[b0 + 1];
    int Tb2 = seqlen[b0 + 2], Tb3 = seqlen[b0 + 3];

    for (int n = 0; n < N_; n++) {
        const float* hprev = g_h2 + (size_t)(n & 1) * (H_ * B_);
        float*       hnext = g_h2 + (size_t)((n & 1) ^ 1) * (H_ * B_);

        // ===== A-partials: gates(ctx part), 36 blocks = 6 j x 6 k ==========
        if (lb < 36) {
            int jblk = lb % 6, ks = lb / 6;
            int k0 = ks * 86, kr = (ks == 5) ? 82 : 86;
            int j = jblk * NT_ + tid;
            for (int i = tid; i < kr; i += NT_)
                *(float4*)&sm_stage[i * 4] =
                    *(const float4*)&g_ctx_t[(size_t)(k0 + i) * 16 + b0];
            __syncthreads();
            float a0 = 0.f, a1 = 0.f, a2 = 0.f, a3 = 0.f;
            const float* wp = g_wct + (size_t)k0 * (3 * H_) + j;
#pragma unroll 8
            for (int i = 0; i < kr; i++) {
                float w = wp[(size_t)i * (3 * H_)];
                float4 c = *(const float4*)&sm_stage[i * 4];
                a0 = fmaf(w, c.x, a0); a1 = fmaf(w, c.y, a1);
                a2 = fmaf(w, c.z, a2); a3 = fmaf(w, c.w, a3);
            }
            float4 r = make_float4(a0, a1, a2, a3);
            *(float4*)&g_pgA[(size_t)((g * KSA + ks) * (3 * H_) + j) * 4] = r;
        }
        flagbar(g_flag[g], lb, SG_, ++tagg);

        // ===== B: h-slice compute + s_t partials (32 blocks = 2 a x 16 k) ==
        if (lb < 32) {
            int ah = lb & 1, ks = lb >> 1;
            int k0 = ks * 64;
            if (tid < 256) {
                int jl = tid >> 2, bl = tid & 3;
                int j = k0 + jl, b = b0 + bl;
                float gi = 0.f, gg = 0.f, go = 0.f;
#pragma unroll
                for (int ks2 = 0; ks2 < KSA; ks2++) {
                    size_t base = (size_t)((g * KSA + ks2) * (3 * H_)) * 4;
                    gi += g_pgA[base + (size_t)j * 4 + bl];
                    gg += g_pgA[base + (size_t)(H_ + j) * 4 + bl];
                    go += g_pgA[base + (size_t)(2 * H_ + j) * 4 + bl];
                }
                size_t row = (size_t)(b * N_ + n) * (3 * H_);
                gi += g_gemb[row + j];
                gg += g_gemb[row + H_ + j];
                go += g_gemb[row + 2 * H_ + j];
                float c_new = fsig(gi) * ftanh(gg);
                float h_new = fsig(go) * ftanh(c_new);
                float h = ZH_ * hprev[j * 16 + b] + (1.0f - ZH_) * h_new;
                sm_h[jl * 4 + bl] = h;
                if (ah == 0) {
                    hnext[j * 16 + b] = h;
                    g_rin[(size_t)(b * N_ + n) * KRO + j] = h;
                }
            }
            __syncthreads();
            int a = ah * 512 + tid;
            float a0 = 0.f, a1 = 0.f, a2 = 0.f, a3 = 0.f;
            const float* wp = g_ws_t + (size_t)k0 * A_ + a;
#pragma unroll 8
            for (int i = 0; i < 64; i++) {
                float w = wp[(size_t)i * A_];
                float4 h = *(const float4*)&sm_h[i * 4];
                a0 = fmaf(w, h.x, a0); a1 = fmaf(w, h.y, a1);
                a2 = fmaf(w, h.z, a2); a3 = fmaf(w, h.w, a3);
            }
            float4 r = make_float4(a0, a1, a2, a3);
            *(float4*)&g_pgB[(size_t)((g * KSB + ks) * A_ + a) * 4] = r;
        }
        flagbar(g_flag[g], lb, SG_, ++tagg);

        // ===== C: s_t reduce + energies (f16x2 tanh) =======================
        {
            int bl = lb & 3;
            int b  = b0 + bl;
            int Tb = (bl == 0) ? Tb0 : (bl == 1) ? Tb1 : (bl == 2) ? Tb2 : Tb3;
            int bi = lb >> 2;
            int K  = (bl == 0) ? 10 : 9;
            for (int i = tid; i < A_; i += NT_) {
                float s = 0.f;
#pragma unroll
                for (int ks = 0; ks < KSB; ks++)
                    s += g_pgB[(size_t)((g * KSB + ks) * A_ + i) * 4 + bl];
                sh_s[i] = s;
            }
            __syncthreads();
            int w = tid >> 5, lane = tid & 31;     // 16 warps
            int Wstride = K * 16;
            const float4* s4 = (const float4*)sh_s;
            const float4* f4 = (const float4*)sm_f;
            for (int t = bi * 16 + w; t < Tb; t += Wstride) {
                float a = g_accum[b * T_ + t];
                unsigned hacc[4] = {0u, 0u, 0u, 0u};
                const float4* ec = (const float4*)g_encctx
                                 + (size_t)(b * T_ + t) * 256;
#pragma unroll
                for (int kk = 0; kk < 8; kk++) {
                    int idx = kk * 32 + lane;
                    float4 e  = ec[idx];
                    float4 sv = s4[idx];
                    float4 fv = f4[idx];
                    float x0 = e.x + fmaf(a, fv.x, sv.x);
                    float x1 = e.y + fmaf(a, fv.y, sv.y);
                    float x2 = e.z + fmaf(a, fv.z, sv.z);
                    float x3 = e.w + fmaf(a, fv.w, sv.w);
                    unsigned t0 = h2tanh(pack_h2(x0, x1));
                    unsigned t1 = h2tanh(pack_h2(x2, x3));
                    HFMA2U(hacc[(2 * kk) & 3], sm_vh[2 * idx], t0);
                    HFMA2U(hacc[(2 * kk + 1) & 3], sm_vh[2 * idx + 1], t1);
                }
                unsigned hs = hadd2u(hadd2u(hacc[0], hacc[1]),
                                     hadd2u(hacc[2], hacc[3]));
                float2 fs = h2f2(hs);
                float acc = fs.x + fs.y;
#pragma unroll
                for (int o = 16; o; o >>= 1)
                    acc += __shfl_down_sync(0xffffffffu, acc, o);
                if (lane == 0) g_energy[b * T_ + t] = acc;
            }
        }
        flagbar(g_flag[g], lb, SG_, ++tagg);

        // ===== D: no-max softmax + context + fertility accum ===============
        if (lb < 32) {
            int bl = lb >> 3, sb = lb & 7;
            int b = b0 + bl, d0 = sb * 64;
            int Tb = (bl == 0) ? Tb0 : (bl == 1) ? Tb1 : (bl == 2) ? Tb2 : Tb3;
            int w = tid >> 5, lane = tid & 31;
            float s = 0.f;
            for (int t = tid; t < Tb; t += NT_) {
                float e = __expf(g_energy[b * T_ + t]);  // |energy| <= ~30
                sw[t] = e;
                s += e;
            }
#pragma unroll
            for (int o = 16; o; o >>= 1)
                s += __shfl_xor_sync(0xffffffffu, s, o);
            if (lane == 0) sm_sum[w] = s;
            __syncthreads();
            float tot = 0.f;
#pragma unroll
            for (int q = 0; q < 16; q++) tot += sm_sum[q];
            float inv = __fdividef(1.0f, tot);
            int dl = tid & 63, ts = tid >> 6;      // 8 t-slices x 64 dims
            float acc = 0.f;
            for (int t = ts; t < Tb; t += 8)
                acc = fmaf(sw[t], enc[(size_t)(b * T_ + t) * D_ + d0 + dl], acc);
            sm_red[ts * 64 + dl] = acc;
            __syncthreads();
            if (tid < 64) {
                float v = 0.f;
#pragma unroll
                for (int q = 0; q < 8; q++) v += sm_red[q * 64 + tid];
                v *= inv;
                int dd = d0 + tid;
                g_ctx_t[dd * 16 + b] = v;
                g_rin[(size_t)(b * N_ + n) * KRO + H_ + E_ + dd] = v;
            }
            if (sb == 0)
                for (int t = tid; t < Tb; t += NT_)
                    g_accum[b * T_ + t] += sw[t] * inv * g_invf[b * T_ + t];
        }
        flagbar(g_flag[g], lb, SG_, ++tagg);
    }
}

// ----------------------------- launch --------------------------------------
extern "C" void kernel_launch(void* const* d_in, const int* in_sizes, int n_in,
                              void* d_out, int out_size) {
    const float* enc     = (const float*)d_in[0];
    const void*  labels  =               d_in[1];
    const int*   seqlen  = (const int*)  d_in[2];
    const float* embed   = (const float*)d_in[3];
    const float* W_ih    = (const float*)d_in[4];
    const float* b_ih    = (const float*)d_in[5];
    const float* b_hh    = (const float*)d_in[6];
    const float* W_s     = (const float*)d_in[7];
    const float* W_encc  = (const float*)d_in[8];
    const float* b_encc  = (const float*)d_in[9];
    const float* v_att   = (const float*)d_in[10];
    const float* W_invf  = (const float*)d_in[11];
    const float* W_fb    = (const float*)d_in[12];
    const float* W_ro    = (const float*)d_in[13];
    const float* b_ro    = (const float*)d_in[14];
    const float* W_out   = (const float*)d_in[15];
    const float* b_out   = (const float*)d_in[16];
    float* out = (float*)d_out;

    float* rin; cudaGetSymbolAddress((void**)&rin, g_rin);
    float* ro;  cudaGetSymbolAddress((void**)&ro,  g_ro);

    k_detect<<<1, 256>>>((const int*)labels);
    k_prep<<<8680, 256>>>(labels, embed, W_ih, b_ih, b_hh, W_s, enc, W_invf);
    k_pregemm<<<504 + 384, 256>>>(enc, W_encc, b_encc);
    k_loop<<<NBLK, NT_>>>(enc, seqlen, v_att, W_fb);
    k_sgemm<<<dim3(P_ / 128, (B_ * N_) / 128), 256>>>(
        rin, KRO, W_ro, b_ro, ro, B_ * N_, P_, KRO, P_ / 2, 1);
    k_sgemm<<<dim3((V_ + 127) / 128, (B_ * N_) / 128), 256>>>(
        ro, P_ / 2, W_out, b_out, out, B_ * N_, V_, P_ / 2, V_, 0);
}

// round 16
// speedup vs baseline: 1.5538x; 1.5538x over previous
#include <cuda_runtime.h>
#include <cuda_bf16.h>
#include <math.h>

#define B_   16
#define T_   500
#define D_   512
#define N_   128
#define E_   640
#define H_   1024
#define A_   1024
#define P_   1024
#define V_   10025
#define KIH  1152              // E_ + D_
#define KRO  2176              // H_ + E_ + D_
#define ZH_  0.05f
#define NBLK 148               // persistent grid: 1 block/SM
#define NG_  4                 // batch groups
#define SG_  37                // blocks per group
#define NT_  512               // threads per loop block
#define KSA  6                 // A-phase k-splits
#define KSB  16                // B-phase k-splits

// ----------------------------- scratch ------------------------------------
__device__ __align__(16) float g_encctx[B_ * T_ * A_];
__device__ __align__(16) float g_invf[B_ * T_];
__device__ __align__(16) float g_h2[2 * H_ * B_];  // double-buffered h [k][b]
__device__ __align__(16) float g_ctx_t[D_ * B_];   // ctx transposed [d][b]
__device__ __align__(16) float g_accum[B_ * T_];
__device__ __align__(16) float g_energy[B_ * T_];
__device__ __align__(16) float g_gemb[B_ * N_ * 3 * H_];
__device__ __align__(16) float g_rin[B_ * N_ * KRO];
__device__ __align__(16) float g_ro[B_ * N_ * (P_ / 2)];
__device__ __align__(16) float g_wih_e[3 * H_ * E_];
__device__ __align__(16) float g_wct[D_ * 3 * H_]; // ctx-part, k-major
__device__ __align__(16) float g_ws_t[H_ * A_];    // W_s^T [k][a]
__device__ __align__(16) float g_b3[3 * H_];
__device__ __align__(16) float g_pgA[NG_ * KSA * 3 * H_ * 4];
__device__ __align__(16) float g_pgB[NG_ * KSB * A_ * 4];
__device__ int   g_lab64;
__device__ unsigned g_barA;
__device__ unsigned g_barG;
__device__ unsigned g_gbarA[NG_ * 32];
__device__ unsigned g_gbarG[NG_ * 32];

// ----------------------------- helpers ------------------------------------
__device__ __forceinline__ float fsig(float x) {
    return __fdividef(1.0f, 1.0f + __expf(-x));
}
__device__ __forceinline__ float ftanh(float x) {
    float a = fabsf(x);
    float e = __expf(-2.0f * a);
    float r = __fdividef(1.0f - e, 1.0f + e);
    return copysignf(r, x);
}
__device__ __forceinline__ unsigned pack_h2(float lo, float hi) {
    unsigned r;
    asm("cvt.rn.f16x2.f32 %0, %1, %2;" : "=r"(r) : "f"(hi), "f"(lo));
    return r;
}
__device__ __forceinline__ unsigned h2tanh(unsigned x) {
    unsigned y;
    asm("tanh.approx.f16x2 %0, %1;" : "=r"(y) : "r"(x));
    return y;
}
#define HFMA2U(acc, a, b) \
    asm("fma.rn.f16x2 %0, %1, %2, %0;" : "+r"(acc) : "r"(a), "r"(b))
__device__ __forceinline__ unsigned hadd2u(unsigned a, unsigned b) {
    unsigned r;
    asm("add.rn.f16x2 %0, %1, %2;" : "=r"(r) : "r"(a), "r"(b));
    return r;
}
__device__ __forceinline__ float2 h2f2(unsigned u) {
    __half2 h;
    memcpy(&h, &u, 4);
    return __half22float2(h);
}
__device__ __forceinline__ unsigned long long packf2(float lo, float hi) {
    unsigned long long r;
    asm("mov.b64 %0, {%1, %2};" : "=l"(r) : "f"(lo), "f"(hi));
    return r;
}
#define FMA2(acc, a, b) \
    asm("fma.rn.f32x2 %0, %1, %2, %0;" : "+l"(acc) : "l"(a), "l"(b))
__device__ __forceinline__ void unpackf2(unsigned long long v, float& lo, float& hi) {
    asm("mov.b64 {%0, %1}, %2;" : "=f"(lo), "=f"(hi) : "l"(v));
}

// ticket barrier: one spinner per block, nanosleep backoff (proven in R13)
__device__ __forceinline__ void barrier_on(unsigned* pa, unsigned* pg, int nb) {
    __syncthreads();
    if (threadIdx.x == 0) {
        unsigned gen, ticket;
        asm volatile("ld.acquire.gpu.u32 %0, [%1];"
                     : "=r"(gen) : "l"(pg) : "memory");
        asm volatile("atom.acq_rel.gpu.add.u32 %0, [%1], 1;"
                     : "=r"(ticket) : "l"(pa) : "memory");
        if (ticket == (unsigned)(nb - 1)) {
            asm volatile("st.relaxed.gpu.u32 [%0], 0;" :: "l"(pa) : "memory");
            unsigned d;
            asm volatile("atom.release.gpu.add.u32 %0, [%1], 1;"
                         : "=r"(d) : "l"(pg) : "memory");
        } else {
            unsigned cur;
            do {
                __nanosleep(32);
                asm volatile("ld.acquire.gpu.u32 %0, [%1];"
                             : "=r"(cur) : "l"(pg) : "memory");
            } while (cur == gen);
        }
    }
    __syncthreads();
}

// ------------------------ labels dtype detection ---------------------------
__global__ void k_detect(const int* __restrict__ lab32) {
    int ok = 1;
    for (int i = threadIdx.x; i < 1024; i += blockDim.x)
        if (lab32[2 * i + 1] != 0) ok = 0;
    int all = __syncthreads_and(ok);
    if (threadIdx.x == 0) g_lab64 = all;
}

// ========== merged prologue: gather | pack | twct | tws | invf =============
__global__ void __launch_bounds__(256) k_prep(const void* __restrict__ labels,
                                              const float* __restrict__ embed,
                                              const float* __restrict__ W_ih,
                                              const float* __restrict__ b_ih,
                                              const float* __restrict__ b_hh,
                                              const float* __restrict__ W_s,
                                              const float* __restrict__ enc,
                                              const float* __restrict__ wf) {
    __shared__ float tl[32][33];
    int bid = blockIdx.x;
    int tid = threadIdx.x;

    if (bid < 2048) {                      // ---- shifted embedding gather
        int row = bid;
        int n = row & (N_ - 1);
        int b = row >> 7;
        float4* dst = (float4*)(g_rin + (size_t)row * KRO + H_);
        if (n == 0) {
            for (int k = tid; k < E_ / 4; k += 256)
                dst[k] = make_float4(0.f, 0.f, 0.f, 0.f);
            return;
        }
        int idx = b * N_ + n - 1;
        int lab = g_lab64 ? (int)((const long long*)labels)[idx]
                          : ((const int*)labels)[idx];
        if (lab < 0) lab = 0;
        if (lab >= V_) lab = V_ - 1;
        const float4* src = (const float4*)(embed + (size_t)lab * E_);
        for (int k = tid; k < E_ / 4; k += 256) dst[k] = src[k];
    } else if (bid < 5120) {               // ---- pack emb-part rows + biases
        int jj = bid - 2048;
        int src = (jj < 1024) ? jj : jj + 1024;
        const float* s = W_ih + (size_t)src * KIH;
        for (int k = tid; k < E_; k += 256)
            g_wih_e[(size_t)jj * E_ + k] = s[k];
        if (tid == 0) g_b3[jj] = b_ih[src] + b_hh[src];
    } else if (bid < 6656) {               // ---- transpose ctx-part of W_ih
        int i = bid - 5120;
        int gc0 = (i % 96) * 32, k0 = (i / 96) * 32;
        int tx = tid & 31, ty = tid >> 5;
        for (int r = ty; r < 32; r += 8) {
            int gc = gc0 + r;
            int src = (gc < 1024) ? gc : gc + 1024;
            tl[r][tx] = W_ih[(size_t)src * KIH + E_ + k0 + tx];
        }
        __syncthreads();
        for (int r = ty; r < 32; r += 8)
            g_wct[(size_t)(k0 + r) * (3 * H_) + gc0 + tx] = tl[tx][r];
    } else if (bid < 7680) {               // ---- transpose W_s
        int i = bid - 6656;
        int j0 = (i % 32) * 32, k0 = (i / 32) * 32;
        int tx = tid & 31, ty = tid >> 5;
        for (int r = ty; r < 32; r += 8)
            tl[r][tx] = W_s[(size_t)(j0 + r) * H_ + k0 + tx];
        __syncthreads();
        for (int r = ty; r < 32; r += 8)
            g_ws_t[(size_t)(k0 + r) * A_ + j0 + tx] = tl[tx][r];
    } else {                               // ---- inverse fertility
        float* wsh = &tl[0][0];
        for (int i = tid; i < D_; i += 256) wsh[i] = wf[i];
        __syncthreads();
        int row  = (bid - 7680) * 8 + (tid >> 5);
        int lane = tid & 31;
        if (row >= B_ * T_) return;
        const float4* ep = (const float4*)(enc + (size_t)row * D_);
        const float4* wp = (const float4*)wsh;
        float acc = 0.0f;
#pragma unroll
        for (int i = 0; i < 4; i++) {
            float4 e = ep[i * 32 + lane];
            float4 w = wp[i * 32 + lane];
            acc = fmaf(e.x, w.x, fmaf(e.y, w.y, fmaf(e.z, w.z, fmaf(e.w, w.w, acc))));
        }
#pragma unroll
        for (int o = 16; o; o >>= 1) acc += __shfl_down_sync(0xffffffffu, acc, o);
        if (lane == 0) g_invf[row] = 0.5f * fsig(acc);
    }
}

// -------- SGEMM tile: C = A·B^T + bias (f32x2 inner) -----------------------
__device__ __forceinline__ void sgemm_tile(const float* __restrict__ A, int lda,
                                           const float* __restrict__ Bm,
                                           const float* __restrict__ bias,
                                           void* __restrict__ C,
                                           int M, int N, int K, int ldc, int mode,
                                           int bx, int by,
                                           float* As, float* Bs) {
    int tid = threadIdx.x;
    int row0 = by * 128, col0 = bx * 128;
    int tx = tid & 15, ty = tid >> 4;
    unsigned long long acc2[8][4];
#pragma unroll
    for (int i = 0; i < 8; i++)
#pragma unroll
        for (int p = 0; p < 4; p++) acc2[i][p] = 0ULL;
    int lr = tid >> 1;
    int lq = (tid & 1) * 4;
    const float* Ap = A  + (size_t)(row0 + lr) * lda + lq;
    const float* Bp = Bm + (size_t)(col0 + lr) * K + lq;
    bool avalid = (row0 + lr) < M;
    bool bvalid = (col0 + lr) < N;
    for (int k0 = 0; k0 < K; k0 += 8) {
        float4 av = avalid ? *(const float4*)(Ap + k0) : make_float4(0, 0, 0, 0);
        float4 bv = bvalid ? *(const float4*)(Bp + k0) : make_float4(0, 0, 0, 0);
        As[(lq + 0) * 128 + lr] = av.x; As[(lq + 1) * 128 + lr] = av.y;
        As[(lq + 2) * 128 + lr] = av.z; As[(lq + 3) * 128 + lr] = av.w;
        Bs[(lq + 0) * 128 + lr] = bv.x; Bs[(lq + 1) * 128 + lr] = bv.y;
        Bs[(lq + 2) * 128 + lr] = bv.z; Bs[(lq + 3) * 128 + lr] = bv.w;
        __syncthreads();
#pragma unroll
        for (int k = 0; k < 8; k++) {
            float ar[8], br[8];
            *(float4*)(ar)     = *(const float4*)&As[k * 128 + ty * 8];
            *(float4*)(ar + 4) = *(const float4*)&As[k * 128 + ty * 8 + 4];
            *(float4*)(br)     = *(const float4*)&Bs[k * 128 + tx * 8];
            *(float4*)(br + 4) = *(const float4*)&Bs[k * 128 + tx * 8 + 4];
            unsigned long long brp[4];
#pragma unroll
            for (int p = 0; p < 4; p++) brp[p] = packf2(br[2 * p], br[2 * p + 1]);
#pragma unroll
            for (int i = 0; i < 8; i++) {
                unsigned long long aa = packf2(ar[i], ar[i]);
#pragma unroll
                for (int p = 0; p < 4; p++) FMA2(acc2[i][p], aa, brp[p]);
            }
        }
        __syncthreads();
    }
    float acc[8][8];
#pragma unroll
    for (int i = 0; i < 8; i++)
#pragma unroll
        for (int p = 0; p < 4; p++)
            unpackf2(acc2[i][p], acc[i][2 * p], acc[i][2 * p + 1]);
    if (mode == 0) {
        float* Cf = (float*)C;
#pragma unroll
        for (int i = 0; i < 8; i++) {
            int m = row0 + ty * 8 + i;
            if (m >= M) break;
#pragma unroll
            for (int j = 0; j < 8; j++) {
                int nn = col0 + tx * 8 + j;
                if (nn < N) Cf[(size_t)m * ldc + nn] = acc[i][j] + bias[nn];
            }
        }
    } else {
        float* Cf = (float*)C;
#pragma unroll
        for (int i = 0; i < 8; i++) {
            int m = row0 + ty * 8 + i;
            if (m >= M) break;
#pragma unroll
            for (int p = 0; p < 4; p++) {
                int nn = col0 + tx * 8 + p * 2;
                float v0 = acc[i][2 * p]     + bias[nn];
                float v1 = acc[i][2 * p + 1] + bias[nn + 1];
                Cf[(size_t)m * ldc + (nn >> 1)] = fmaxf(v0, v1);
            }
        }
    }
}

// ---- fused pre-GEMMs ------------------------------------------------------
__global__ void __launch_bounds__(256) k_pregemm(const float* __restrict__ enc,
                                                 const float* __restrict__ W_encc,
                                                 const float* __restrict__ b_encc) {
    __shared__ float As[8 * 128], Bs[8 * 128];
    int bid = blockIdx.x;
    if (bid < 504) {
        sgemm_tile(enc, D_, W_encc, b_encc, (void*)g_encctx,
                   B_ * T_, A_, D_, A_, 0, bid % 8, bid / 8, As, Bs);
    } else {
        int i = bid - 504;
        sgemm_tile(g_rin + H_, KRO, g_wih_e, g_b3, (void*)g_gemb,
                   B_ * N_, 3 * H_, E_, 3 * H_, 0, i % 24, i / 24, As, Bs);
    }
}

// --------------------------- post GEMMs ------------------------------------
__global__ void __launch_bounds__(256) k_sgemm(const float* __restrict__ A, int lda,
                                               const float* __restrict__ Bm,
                                               const float* __restrict__ bias,
                                               float* __restrict__ C,
                                               int M, int N, int K, int ldc,
                                               int mode) {
    __shared__ float As[8 * 128], Bs[8 * 128];
    sgemm_tile(A, lda, Bm, bias, (void*)C, M, N, K, ldc, mode,
               blockIdx.x, blockIdx.y, As, Bs);
}

// ====== persistent recurrence: 4 async groups, 512-thread blocks ===========
__global__ void __launch_bounds__(NT_) k_loop(const float* __restrict__ enc,
                                              const int* __restrict__ seqlen,
                                              const float* __restrict__ v_att,
                                              const float* __restrict__ W_fb) {
    __shared__ float sm_f[A_];
    __shared__ __align__(16) unsigned sm_vh[A_ / 2];
    __shared__ float sh_s[A_];
    __shared__ float sm_red[NT_];
    __shared__ float sm_sum[16];
    __shared__ float sw[512];
    __shared__ __align__(16) float sm_stage[86 * 16];   // A ctx staging
    __shared__ __align__(16) float sm_h[64 * 4];        // B h slice
    int tid = threadIdx.x;
    int bk  = blockIdx.x;
    int g   = bk / SG_;
    int lb  = bk % SG_;
    int b0  = g * 4;
    unsigned* gbA = &g_gbarA[g * 32];
    unsigned* gbG = &g_gbarG[g * 32];
    int gw  = bk * NT_ + tid;

    for (int i = tid; i < A_; i += NT_) sm_f[i] = W_fb[i];
    for (int i = tid; i < A_ / 2; i += NT_)
        sm_vh[i] = pack_h2(v_att[2 * i], v_att[2 * i + 1]);
    for (int i = gw; i < 2 * H_ * B_; i += NBLK * NT_) g_h2[i]  = 0.0f;
    for (int i = gw; i < D_ * B_; i += NBLK * NT_) g_ctx_t[i]   = 0.0f;
    for (int i = gw; i < B_ * T_; i += NBLK * NT_) g_accum[i]   = 0.0f;
    barrier_on(&g_barA, &g_barG, NBLK);

    int Tb0 = seqlen[b0 + 0], Tb1 = seqlen[b0 + 1];
    int Tb2 = seqlen[b0 + 2], Tb3 = seqlen[b0 + 3];

    for (int n = 0; n < N_; n++) {
        const float* hprev = g_h2 + (size_t)(n & 1) * (H_ * B_);
        float*       hnext = g_h2 + (size_t)((n & 1) ^ 1) * (H_ * B_);

        // ===== A-partials: gates(ctx part), 36 blocks = 6 j x 6 k ==========
        if (lb < 36) {
            int jblk = lb % 6, ks = lb / 6;
            int k0 = ks * 86, kr = (ks == 5) ? 82 : 86;
            int j = jblk * NT_ + tid;
            for (int i = tid; i < kr; i += NT_)
                *(float4*)&sm_stage[i * 4] =
                    *(const float4*)&g_ctx_t[(size_t)(k0 + i) * 16 + b0];
            __syncthreads();
            float a0 = 0.f, a1 = 0.f, a2 = 0.f, a3 = 0.f;
            const float* wp = g_wct + (size_t)k0 * (3 * H_) + j;
#pragma unroll 8
            for (int i = 0; i < kr; i++) {
                float w = wp[(size_t)i * (3 * H_)];
                float4 c = *(const float4*)&sm_stage[i * 4];
                a0 = fmaf(w, c.x, a0); a1 = fmaf(w, c.y, a1);
                a2 = fmaf(w, c.z, a2); a3 = fmaf(w, c.w, a3);
            }
            float4 r = make_float4(a0, a1, a2, a3);
            *(float4*)&g_pgA[(size_t)((g * KSA + ks) * (3 * H_) + j) * 4] = r;
        }
        barrier_on(gbA, gbG, SG_);

        // ===== B: h-slice compute + s_t partials (32 blocks = 2 a x 16 k) ==
        if (lb < 32) {
            int ah = lb & 1, ks = lb >> 1;
            int k0 = ks * 64;
            if (tid < 256) {
                int jl = tid >> 2, bl = tid & 3;
                int j = k0 + jl, b = b0 + bl;
                float gi = 0.f, gg = 0.f, go = 0.f;
#pragma unroll
                for (int ks2 = 0; ks2 < KSA; ks2++) {
                    size_t base = (size_t)((g * KSA + ks2) * (3 * H_)) * 4;
                    gi += g_pgA[base + (size_t)j * 4 + bl];
                    gg += g_pgA[base + (size_t)(H_ + j) * 4 + bl];
                    go += g_pgA[base + (size_t)(2 * H_ + j) * 4 + bl];
                }
                size_t row = (size_t)(b * N_ + n) * (3 * H_);
                gi += g_gemb[row + j];
                gg += g_gemb[row + H_ + j];
                go += g_gemb[row + 2 * H_ + j];
                float c_new = fsig(gi) * ftanh(gg);
                float h_new = fsig(go) * ftanh(c_new);
                float h = ZH_ * hprev[j * 16 + b] + (1.0f - ZH_) * h_new;
                sm_h[jl * 4 + bl] = h;
                if (ah == 0) {
                    hnext[j * 16 + b] = h;
                    g_rin[(size_t)(b * N_ + n) * KRO + j] = h;
                }
            }
            __syncthreads();
            int a = ah * 512 + tid;
            float a0 = 0.f, a1 = 0.f, a2 = 0.f, a3 = 0.f;
            const float* wp = g_ws_t + (size_t)k0 * A_ + a;
#pragma unroll 8
            for (int i = 0; i < 64; i++) {
                float w = wp[(size_t)i * A_];
                float4 h = *(const float4*)&sm_h[i * 4];
                a0 = fmaf(w, h.x, a0); a1 = fmaf(w, h.y, a1);
                a2 = fmaf(w, h.z, a2); a3 = fmaf(w, h.w, a3);
            }
            float4 r = make_float4(a0, a1, a2, a3);
            *(float4*)&g_pgB[(size_t)((g * KSB + ks) * A_ + a) * 4] = r;
        }
        barrier_on(gbA, gbG, SG_);

        // ===== C: s_t reduce + energies (f16x2 tanh) =======================
        {
            int bl = lb & 3;
            int b  = b0 + bl;
            int Tb = (bl == 0) ? Tb0 : (bl == 1) ? Tb1 : (bl == 2) ? Tb2 : Tb3;
            int bi = lb >> 2;
            int K  = (bl == 0) ? 10 : 9;
            for (int i = tid; i < A_; i += NT_) {
                float s = 0.f;
#pragma unroll
                for (int ks = 0; ks < KSB; ks++)
                    s += g_pgB[(size_t)((g * KSB + ks) * A_ + i) * 4 + bl];
                sh_s[i] = s;
            }
            __syncthreads();
            int w = tid >> 5, lane = tid & 31;     // 16 warps
            int Wstride = K * 16;
            const float4* s4 = (const float4*)sh_s;
            const float4* f4 = (const float4*)sm_f;
            for (int t = bi * 16 + w; t < Tb; t += Wstride) {
                float a = g_accum[b * T_ + t];
                unsigned hacc[4] = {0u, 0u, 0u, 0u};
                const float4* ec = (const float4*)g_encctx
                                 + (size_t)(b * T_ + t) * 256;
#pragma unroll
                for (int kk = 0; kk < 8; kk++) {
                    int idx = kk * 32 + lane;
                    float4 e  = ec[idx];
                    float4 sv = s4[idx];
                    float4 fv = f4[idx];
                    float x0 = e.x + fmaf(a, fv.x, sv.x);
                    float x1 = e.y + fmaf(a, fv.y, sv.y);
                    float x2 = e.z + fmaf(a, fv.z, sv.z);
                    float x3 = e.w + fmaf(a, fv.w, sv.w);
                    unsigned t0 = h2tanh(pack_h2(x0, x1));
                    unsigned t1 = h2tanh(pack_h2(x2, x3));
                    HFMA2U(hacc[(2 * kk) & 3], sm_vh[2 * idx], t0);
                    HFMA2U(hacc[(2 * kk + 1) & 3], sm_vh[2 * idx + 1], t1);
                }
                unsigned hs = hadd2u(hadd2u(hacc[0], hacc[1]),
                                     hadd2u(hacc[2], hacc[3]));
                float2 fs = h2f2(hs);
                float acc = fs.x + fs.y;
#pragma unroll
                for (int o = 16; o; o >>= 1)
                    acc += __shfl_down_sync(0xffffffffu, acc, o);
                if (lane == 0) g_energy[b * T_ + t] = acc;
            }
        }
        barrier_on(gbA, gbG, SG_);

        // ===== D: no-max softmax + context + fertility accum ===============
        if (lb < 32) {
            int bl = lb >> 3, sb = lb & 7;
            int b = b0 + bl, d0 = sb * 64;
            int Tb = (bl == 0) ? Tb0 : (bl == 1) ? Tb1 : (bl == 2) ? Tb2 : Tb3;
            int w = tid >> 5, lane = tid & 31;
            float s = 0.f;
            for (int t = tid; t < Tb; t += NT_) {
                float e = __expf(g_energy[b * T_ + t]);  // |energy| <= ~30
                sw[t] = e;
                s += e;
            }
#pragma unroll
            for (int o = 16; o; o >>= 1)
                s += __shfl_xor_sync(0xffffffffu, s, o);
            if (lane == 0) sm_sum[w] = s;
            __syncthreads();
            float tot = 0.f;
#pragma unroll
            for (int q = 0; q < 16; q++) tot += sm_sum[q];
            float inv = __fdividef(1.0f, tot);
            int dl = tid & 63, ts = tid >> 6;      // 8 t-slices x 64 dims
            float acc = 0.f;
            for (int t = ts; t < Tb; t += 8)
                acc = fmaf(sw[t], enc[(size_t)(b * T_ + t) * D_ + d0 + dl], acc);
            sm_red[ts * 64 + dl] = acc;
            __syncthreads();
            if (tid < 64) {
                float v = 0.f;
#pragma unroll
                for (int q = 0; q < 8; q++) v += sm_red[q * 64 + tid];
                v *= inv;
                int dd = d0 + tid;
                g_ctx_t[dd * 16 + b] = v;
                g_rin[(size_t)(b * N_ + n) * KRO + H_ + E_ + dd] = v;
            }
            if (sb == 0)
                for (int t = tid; t < Tb; t += NT_)
                    g_accum[b * T_ + t] += sw[t] * inv * g_invf[b * T_ + t];
        }
        barrier_on(gbA, gbG, SG_);
    }
}

// ----------------------------- launch --------------------------------------
extern "C" void kernel_launch(void* const* d_in, const int* in_sizes, int n_in,
                              void* d_out, int out_size) {
    const float* enc     = (const float*)d_in[0];
    const void*  labels  =               d_in[1];
    const int*   seqlen  = (const int*)  d_in[2];
    const float* embed   = (const float*)d_in[3];
    const float* W_ih    = (const float*)d_in[4];
    const float* b_ih    = (const float*)d_in[5];
    const float* b_hh    = (const float*)d_in[6];
    const float* W_s     = (const float*)d_in[7];
    const float* W_encc  = (const float*)d_in[8];
    const float* b_encc  = (const float*)d_in[9];
    const float* v_att   = (const float*)d_in[10];
    const float* W_invf  = (const float*)d_in[11];
    const float* W_fb    = (const float*)d_in[12];
    const float* W_ro    = (const float*)d_in[13];
    const float* b_ro    = (const float*)d_in[14];
    const float* W_out   = (const float*)d_in[15];
    const float* b_out   = (const float*)d_in[16];
    float* out = (float*)d_out;

    float* rin; cudaGetSymbolAddress((void**)&rin, g_rin);
    float* ro;  cudaGetSymbolAddress((void**)&ro,  g_ro);

    k_detect<<<1, 256>>>((const int*)labels);
    k_prep<<<8680, 256>>>(labels, embed, W_ih, b_ih, b_hh, W_s, enc, W_invf);
    k_pregemm<<<504 + 384, 256>>>(enc, W_encc, b_encc);
    k_loop<<<NBLK, NT_>>>(enc, seqlen, v_att, W_fb);
    k_sgemm<<<dim3(P_ / 128, (B_ * N_) / 128), 256>>>(
        rin, KRO, W_ro, b_ro, ro, B_ * N_, P_, KRO, P_ / 2, 1);
    k_sgemm<<<dim3((V_ + 127) / 128, (B_ * N_) / 128), 256>>>(
        ro, P_ / 2, W_out, b_out, out, B_ * N_, V_, P_ / 2, V_, 0);
}